// round 8
// baseline (speedup 1.0000x reference)
#include <cuda_runtime.h>
#include <cstdint>
#include <cstddef>

#define IN_F   4096
#define OUT_F  11008
#define BATCH  32
#define N_TILE 32
#define K_TILE 64
#define STAGES 4
#define THREADS 128
#define NITER  (IN_F / K_TILE)      // 64

#define XROW    80                   // 64B data + 16B pad: conflict-free LDS.32
#define XSTAGE  (64 * XROW)          // 5120 B per k-stage
// g_xq tiled layout: [NITER][64 rows][XROW]; rows 0..31 = q1 plane, 32..63 = q2 plane

__device__ __align__(128) signed char g_xq[NITER * XSTAGE];

__global__ void quantize_x_kernel(const float* __restrict__ x) {
    int i = blockIdx.x * blockDim.x + threadIdx.x;      // i = b*4096 + k
    if (i >= BATCH * IN_F) return;
    int b = i >> 12, k = i & 4095;
    float v  = x[i];
    float q1 = rintf(v * 16.0f);
    q1 = fminf(fmaxf(q1, -127.0f), 127.0f);
    float r  = v - q1 * 0.0625f;
    float q2 = rintf(r * 4096.0f);
    q2 = fminf(fmaxf(q2, -127.0f), 127.0f);
    int tile = k >> 6, off = k & 63;
    signed char* base = g_xq + tile * XSTAGE + off;
    base[(size_t)b * XROW]        = (signed char)(int)q1;
    base[(size_t)(b + 32) * XROW] = (signed char)(int)q2;
}

__device__ __forceinline__ void cp_async16(void* sdst, const void* gsrc) {
    uint32_t s = (uint32_t)__cvta_generic_to_shared(sdst);
    asm volatile("cp.async.cg.shared.global [%0], [%1], 16;" :: "r"(s), "l"(gsrc));
}

__device__ __forceinline__ void mma_s8(int d[4], const int a[4], const int b[2]) {
    asm volatile(
        "mma.sync.aligned.m16n8k32.row.col.s32.s8.s8.s32 "
        "{%0,%1,%2,%3}, {%4,%5,%6,%7}, {%8,%9}, {%0,%1,%2,%3};"
        : "+r"(d[0]), "+r"(d[1]), "+r"(d[2]), "+r"(d[3])
        : "r"(a[0]), "r"(a[1]), "r"(a[2]), "r"(a[3]), "r"(b[0]), "r"(b[1]));
}

// W arrives as int32 words (one weight per word, value in [-128,127]); low byte
// is the int8 value. W streams straight from global via LDG.128 + PRMT (no
// LDGSTS issue cost); X comes from a 4-deep smem ring filled with plain
// cp.async (256 chunks/stage — negligible issue cost).
__global__ __launch_bounds__(THREADS, 3)
void qlinear_gemm_i32(const int* __restrict__ W32,
                      const float* __restrict__ scale_p,
                      const float* __restrict__ bias,
                      float* __restrict__ out) {
    __shared__ __align__(128) char xsm[STAGES * XSTAGE];

    const int tid  = threadIdx.x;
    const int n0   = blockIdx.x * N_TILE;
    const int lane = tid & 31;
    const int warp = tid >> 5;       // 4 warps; warp owns n-cols [warp*8, warp*8+8)
    const int g    = lane >> 2;      // 0..7
    const int q    = lane & 3;       // 0..3

    auto load_stage = [&](int s, int tile) {
        // 64 rows x 4 chunks = 256 chunks; 2 per thread. Same padded layout in
        // gmem and smem, so only data chunks are copied.
        char* xbase = xsm + s * XSTAGE;
        const signed char* src = g_xq + (size_t)tile * XSTAGE;
        #pragma unroll
        for (int i = 0; i < 2; ++i) {
            int c   = i * THREADS + tid;
            int row = c >> 2, cb = c & 3;
            cp_async16(xbase + row * XROW + cb * 16,
                       src + row * XROW + cb * 16);
        }
    };

    int acc[4][4];   // [m_tile][reg]; t 0..1 = q1 plane (rows 0..31), 2..3 = q2 plane
    #pragma unroll
    for (int t = 0; t < 4; ++t)
        #pragma unroll
        for (int r = 0; r < 4; ++r) acc[t][r] = 0;

    #pragma unroll
    for (int s = 0; s < STAGES - 1; ++s) {
        load_stage(s, s);
        asm volatile("cp.async.commit_group;");
    }

    const int nloc = warp * 8 + g;
    const int* wp = W32 + (size_t)(n0 + nloc) * IN_F + q * 4;

    // Software-prefetch W one iteration ahead (keeps 8 LDG.128 in flight/warp).
    int4 wc[4], wn[4];
    #pragma unroll
    for (int j = 0; j < 4; ++j) wc[j] = __ldcs((const int4*)(wp + j * 16));

    for (int it = 0; it < NITER; ++it) {
        asm volatile("cp.async.wait_group %0;" :: "n"(STAGES - 2));
        __syncthreads();
        const int s = it & (STAGES - 1);

        if (it + 1 < NITER) {
            const int* wpn = wp + (it + 1) * K_TILE;
            #pragma unroll
            for (int j = 0; j < 4; ++j) wn[j] = __ldcs((const int4*)(wpn + j * 16));
        }

        const char* xst = xsm + s * XSTAGE;
        #pragma unroll
        for (int ks = 0; ks < 2; ++ks) {
            const int kb = ks * 32 + q * 4;
            int a[4][4];
            #pragma unroll
            for (int t = 0; t < 4; ++t) {
                const char* xr = xst + (t * 16 + g) * XROW;
                a[t][0] = *(const int*)(xr + kb);
                a[t][1] = *(const int*)(xr + 8 * XROW + kb);
                a[t][2] = *(const int*)(xr + kb + 16);
                a[t][3] = *(const int*)(xr + 8 * XROW + kb + 16);
            }
            const int4 w0 = wc[ks * 2];       // words kb..kb+3
            const int4 w1 = wc[ks * 2 + 1];   // words kb+16..kb+19
            int b[2];
            b[0] = __byte_perm(__byte_perm(w0.x, w0.y, 0x0040),
                               __byte_perm(w0.z, w0.w, 0x0040), 0x5410);
            b[1] = __byte_perm(__byte_perm(w1.x, w1.y, 0x0040),
                               __byte_perm(w1.z, w1.w, 0x0040), 0x5410);
            #pragma unroll
            for (int t = 0; t < 4; ++t)
                mma_s8(acc[t], a[t], b);
        }

        const int pf = it + STAGES - 1;
        if (pf < NITER) load_stage(pf & (STAGES - 1), pf);
        asm volatile("cp.async.commit_group;");

        #pragma unroll
        for (int j = 0; j < 4; ++j) wc[j] = wn[j];
    }

    // Epilogue: out = scale * (acc_hi/16 + acc_lo/4096) + bias
    const float sc = __ldg(scale_p);
    const float s1 = 0.0625f;
    const float s2 = 1.0f / 4096.0f;
    #pragma unroll
    for (int t = 0; t < 2; ++t) {
        const int n = n0 + warp * 8 + q * 2;
        const float2 bb = *(const float2*)&bias[n];
        const int r0 = t * 16 + g;
        const int r1 = r0 + 8;
        float v0 = fmaf(sc, fmaf(s1, (float)acc[t][0], s2 * (float)acc[t + 2][0]), bb.x);
        float v1 = fmaf(sc, fmaf(s1, (float)acc[t][1], s2 * (float)acc[t + 2][1]), bb.y);
        float v2 = fmaf(sc, fmaf(s1, (float)acc[t][2], s2 * (float)acc[t + 2][2]), bb.x);
        float v3 = fmaf(sc, fmaf(s1, (float)acc[t][3], s2 * (float)acc[t + 2][3]), bb.y);
        *(float2*)&out[(size_t)r0 * OUT_F + n] = make_float2(v0, v1);
        *(float2*)&out[(size_t)r1 * OUT_F + n] = make_float2(v2, v3);
    }
}

extern "C" void kernel_launch(void* const* d_in, const int* in_sizes, int n_in,
                              void* d_out, int out_size) {
    // Bind inputs by element count (ordering-proof): all four counts are distinct.
    const float* x = nullptr; const void* w = nullptr;
    const float* scale = nullptr; const float* bias = nullptr;
    for (int i = 0; i < n_in; ++i) {
        switch (in_sizes[i]) {
            case BATCH * IN_F:    x     = (const float*)d_in[i]; break;
            case OUT_F * IN_F:    w     = d_in[i];               break;
            case 1:               scale = (const float*)d_in[i]; break;
            case OUT_F:           bias  = (const float*)d_in[i]; break;
        }
    }
    float* out = (float*)d_out;

    quantize_x_kernel<<<(BATCH * IN_F + 255) / 256, 256>>>(x);
    qlinear_gemm_i32<<<OUT_F / N_TILE, THREADS>>>((const int*)w, scale, bias, out);
}

// round 9
// speedup vs baseline: 1.6636x; 1.6636x over previous
#include <cuda_runtime.h>
#include <cuda.h>
#include <cstdint>
#include <cstddef>

#define IN_F   4096
#define OUT_F  11008
#define BATCH  32
#define N_TILE 32
#define K_TILE 64
#define STAGES 4
#define THREADS 128
#define NITER  (IN_F / K_TILE)      // 64

#define XROW    80                   // 64B data + 16B pad: conflict-free LDS.32
#define XSTAGE  (64 * XROW)          // 5120 B per k-stage
#define WSTAGE  (N_TILE * K_TILE * 4)        // 8192 B (raw int32 words)
#define DSM_W   (STAGES * WSTAGE)            // 32768
#define DSM_X   (STAGES * XSTAGE)            // 20480
#define DSM_TOTAL (DSM_W + DSM_X)            // 53248

// g_xq tiled layout: [NITER][64 rows][XROW]; rows 0..31 = q1 plane, 32..63 = q2 plane
__device__ __align__(128) signed char g_xq[NITER * XSTAGE];

__global__ void quantize_x_kernel(const float* __restrict__ x) {
    int i = blockIdx.x * blockDim.x + threadIdx.x;      // i = b*4096 + k
    if (i >= BATCH * IN_F) return;
    int b = i >> 12, k = i & 4095;
    float v  = x[i];
    float q1 = rintf(v * 16.0f);
    q1 = fminf(fmaxf(q1, -127.0f), 127.0f);
    float r  = v - q1 * 0.0625f;
    float q2 = rintf(r * 4096.0f);
    q2 = fminf(fmaxf(q2, -127.0f), 127.0f);
    int tile = k >> 6, off = k & 63;
    signed char* base = g_xq + tile * XSTAGE + off;
    base[(size_t)b * XROW]        = (signed char)(int)q1;
    base[(size_t)(b + 32) * XROW] = (signed char)(int)q2;
}

__device__ __forceinline__ uint32_t smem_u32(const void* p) {
    return (uint32_t)__cvta_generic_to_shared(p);
}
__device__ __forceinline__ void cp_async16(void* sdst, const void* gsrc) {
    asm volatile("cp.async.cg.shared.global [%0], [%1], 16;"
                 :: "r"(smem_u32(sdst)), "l"(gsrc));
}
__device__ __forceinline__ void mbar_init(uint32_t bar, uint32_t cnt) {
    asm volatile("mbarrier.init.shared.b64 [%0], %1;" :: "r"(bar), "r"(cnt) : "memory");
}
__device__ __forceinline__ void mbar_expect_tx(uint32_t bar, uint32_t bytes) {
    asm volatile("mbarrier.arrive.expect_tx.shared.b64 _, [%0], %1;"
                 :: "r"(bar), "r"(bytes) : "memory");
}
__device__ __forceinline__ void tma_load_2d(uint32_t sdst, const CUtensorMap* map,
                                            int cx, int cy, uint32_t bar) {
    asm volatile(
        "cp.async.bulk.tensor.2d.shared::cta.global.tile.mbarrier::complete_tx::bytes "
        "[%0], [%1, {%2, %3}], [%4];"
        :: "r"(sdst), "l"(map), "r"(cx), "r"(cy), "r"(bar) : "memory");
}
__device__ __forceinline__ void mbar_wait(uint32_t bar, uint32_t parity) {
    uint32_t done;
    asm volatile(
        "{\n\t.reg .pred p;\n\t"
        "mbarrier.try_wait.parity.acquire.cta.shared::cta.b64 p, [%1], %2;\n\t"
        "selp.b32 %0, 1, 0, p;\n\t}"
        : "=r"(done) : "r"(bar), "r"(parity) : "memory");
    if (!done) {
        asm volatile(
            "{\n\t.reg .pred P1;\n\t"
            "WAIT_LOOP_%=:\n\t"
            "mbarrier.try_wait.parity.acquire.cta.shared::cta.b64 P1, [%0], %1, 0x989680;\n\t"
            "@P1 bra.uni WAIT_DONE_%=;\n\t"
            "bra.uni WAIT_LOOP_%=;\n\t"
            "WAIT_DONE_%=:\n\t}"
            :: "r"(bar), "r"(parity) : "memory");
    }
}
__device__ __forceinline__ void mma_s8(int d[4], const int a[4], const int b[2]) {
    asm volatile(
        "mma.sync.aligned.m16n8k32.row.col.s32.s8.s8.s32 "
        "{%0,%1,%2,%3}, {%4,%5,%6,%7}, {%8,%9}, {%0,%1,%2,%3};"
        : "+r"(d[0]), "+r"(d[1]), "+r"(d[2]), "+r"(d[3])
        : "r"(a[0]), "r"(a[1]), "r"(a[2]), "r"(a[3]), "r"(b[0]), "r"(b[1]));
}

// W arrives as int32 words (one weight per word, value in [-128,127]); low byte
// is the int8 value. W streams via the TMA engine (8KB tensor tile per stage,
// no per-thread load issue cost); X uses the proven cp.async ring.
__global__ __launch_bounds__(THREADS, 3)
void qlinear_gemm_tma(const __grid_constant__ CUtensorMap tmap,
                      const float* __restrict__ scale_p,
                      const float* __restrict__ bias,
                      float* __restrict__ out) {
    extern __shared__ __align__(128) char dsm[];
    char* wsm = dsm;            // [STAGES][32 rows][256B]
    char* xsm = dsm + DSM_W;    // [STAGES][64 rows][80B]
    __shared__ __align__(8) unsigned long long mbar_store[STAGES];

    const int tid  = threadIdx.x;
    const int n0   = blockIdx.x * N_TILE;
    const int lane = tid & 31;
    const int warp = tid >> 5;       // 4 warps; warp owns n-cols [warp*8, warp*8+8)
    const int g    = lane >> 2;      // 0..7
    const int q    = lane & 3;       // 0..3
    const uint32_t mbar0 = smem_u32(mbar_store);

    auto load_x = [&](int s, int tile) {
        char* xbase = xsm + s * XSTAGE;
        const signed char* src = g_xq + (size_t)tile * XSTAGE;
        #pragma unroll
        for (int i = 0; i < 2; ++i) {
            int c   = i * THREADS + tid;
            int row = c >> 2, cb = c & 3;
            cp_async16(xbase + row * XROW + cb * 16, src + row * XROW + cb * 16);
        }
    };

    if (tid == 0) {
        #pragma unroll
        for (int s = 0; s < STAGES; ++s) mbar_init(mbar0 + 8u * s, 1);
    }
    __syncthreads();

    // Prologue: fill STAGES-1 stages of both rings.
    #pragma unroll
    for (int s = 0; s < STAGES - 1; ++s) {
        if (tid == 0) {
            mbar_expect_tx(mbar0 + 8u * s, WSTAGE);
            tma_load_2d(smem_u32(wsm) + s * WSTAGE, &tmap, s * K_TILE, n0, mbar0 + 8u * s);
        }
        load_x(s, s);
        asm volatile("cp.async.commit_group;");
    }

    int acc[4][4];   // [m_tile][reg]; t 0..1 = q1 plane (rows 0..31), 2..3 = q2 plane
    #pragma unroll
    for (int t = 0; t < 4; ++t)
        #pragma unroll
        for (int r = 0; r < 4; ++r) acc[t][r] = 0;

    const int nloc = warp * 8 + g;

    for (int it = 0; it < NITER; ++it) {
        const int s = it & (STAGES - 1);
        asm volatile("cp.async.wait_group %0;" :: "n"(STAGES - 2));
        mbar_wait(mbar0 + 8u * s, (it >> 2) & 1);
        __syncthreads();

        // Refill stage consumed before the barrier above.
        const int pf = it + STAGES - 1;
        if (pf < NITER) {
            const int b = pf & (STAGES - 1);
            if (tid == 0) {
                mbar_expect_tx(mbar0 + 8u * b, WSTAGE);
                tma_load_2d(smem_u32(wsm) + b * WSTAGE, &tmap, pf * K_TILE, n0, mbar0 + 8u * b);
            }
            load_x(b, pf);
        }
        asm volatile("cp.async.commit_group;");

        const char* wst = wsm + s * WSTAGE;
        const char* xst = xsm + s * XSTAGE;
        #pragma unroll
        for (int ks = 0; ks < 2; ++ks) {
            const int kb = ks * 32 + q * 4;
            int a[4][4];
            #pragma unroll
            for (int t = 0; t < 4; ++t) {
                const char* xr = xst + (t * 16 + g) * XROW;
                a[t][0] = *(const int*)(xr + kb);
                a[t][1] = *(const int*)(xr + 8 * XROW + kb);
                a[t][2] = *(const int*)(xr + kb + 16);
                a[t][3] = *(const int*)(xr + 8 * XROW + kb + 16);
            }
            const char* wr = wst + nloc * 256 + ks * 128 + q * 16;
            const int4 w0 = *(const int4*)wr;          // words kb..kb+3
            const int4 w1 = *(const int4*)(wr + 64);   // words kb+16..kb+19
            int b[2];
            b[0] = __byte_perm(__byte_perm(w0.x, w0.y, 0x0040),
                               __byte_perm(w0.z, w0.w, 0x0040), 0x5410);
            b[1] = __byte_perm(__byte_perm(w1.x, w1.y, 0x0040),
                               __byte_perm(w1.z, w1.w, 0x0040), 0x5410);
            #pragma unroll
            for (int t = 0; t < 4; ++t)
                mma_s8(acc[t], a[t], b);
        }
    }

    // Epilogue: out = scale * (acc_hi/16 + acc_lo/4096) + bias
    const float sc = __ldg(scale_p);
    const float s1 = 0.0625f;
    const float s2 = 1.0f / 4096.0f;
    #pragma unroll
    for (int t = 0; t < 2; ++t) {
        const int n = n0 + warp * 8 + q * 2;
        const float2 bb = *(const float2*)&bias[n];
        const int r0 = t * 16 + g;
        const int r1 = r0 + 8;
        float v0 = fmaf(sc, fmaf(s1, (float)acc[t][0], s2 * (float)acc[t + 2][0]), bb.x);
        float v1 = fmaf(sc, fmaf(s1, (float)acc[t][1], s2 * (float)acc[t + 2][1]), bb.y);
        float v2 = fmaf(sc, fmaf(s1, (float)acc[t][2], s2 * (float)acc[t + 2][2]), bb.x);
        float v3 = fmaf(sc, fmaf(s1, (float)acc[t][3], s2 * (float)acc[t + 2][3]), bb.y);
        *(float2*)&out[(size_t)r0 * OUT_F + n] = make_float2(v0, v1);
        *(float2*)&out[(size_t)r1 * OUT_F + n] = make_float2(v2, v3);
    }
}

typedef CUresult (*EncodeTiledFn)(
    CUtensorMap*, CUtensorMapDataType, cuuint32_t, void*,
    const cuuint64_t*, const cuuint64_t*, const cuuint32_t*, const cuuint32_t*,
    CUtensorMapInterleave, CUtensorMapSwizzle, CUtensorMapL2promotion,
    CUtensorMapFloatOOBfill);

extern "C" void kernel_launch(void* const* d_in, const int* in_sizes, int n_in,
                              void* d_out, int out_size) {
    // Bind inputs by element count (ordering-proof): all four counts are distinct.
    const float* x = nullptr; void* w = nullptr;
    const float* scale = nullptr; const float* bias = nullptr;
    for (int i = 0; i < n_in; ++i) {
        switch (in_sizes[i]) {
            case BATCH * IN_F:    x     = (const float*)d_in[i]; break;
            case OUT_F * IN_F:    w     = (void*)d_in[i];        break;
            case 1:               scale = (const float*)d_in[i]; break;
            case OUT_F:           bias  = (const float*)d_in[i]; break;
        }
    }
    float* out = (float*)d_out;

    static EncodeTiledFn encode_fn = nullptr;
    static bool attr_done = false;
    if (!encode_fn) {
        cudaDriverEntryPointQueryResult qr;
        void* fp = nullptr;
        cudaGetDriverEntryPoint("cuTensorMapEncodeTiled", &fp,
                                cudaEnableDefault, &qr);
        encode_fn = (EncodeTiledFn)fp;
    }
    if (!attr_done) {
        cudaFuncSetAttribute(qlinear_gemm_tma,
                             cudaFuncAttributeMaxDynamicSharedMemorySize, DSM_TOTAL);
        attr_done = true;
    }

    // 2D map over W as uint32: dim0 = IN_F words (row), dim1 = OUT_F rows.
    CUtensorMap tmap;
    cuuint64_t dims[2]    = {IN_F, OUT_F};
    cuuint64_t strides[1] = {IN_F * sizeof(int)};
    cuuint32_t box[2]     = {K_TILE, N_TILE};
    cuuint32_t estr[2]    = {1, 1};
    encode_fn(&tmap, CU_TENSOR_MAP_DATA_TYPE_UINT32, 2, w,
              dims, strides, box, estr,
              CU_TENSOR_MAP_INTERLEAVE_NONE, CU_TENSOR_MAP_SWIZZLE_NONE,
              CU_TENSOR_MAP_L2_PROMOTION_L2_128B, CU_TENSOR_MAP_FLOAT_OOB_FILL_NONE);

    quantize_x_kernel<<<(BATCH * IN_F + 255) / 256, 256>>>(x);
    qlinear_gemm_tma<<<OUT_F / N_TILE, THREADS, DSM_TOTAL>>>(tmap, scale, bias, out);
}

// round 10
// speedup vs baseline: 1.6754x; 1.0071x over previous
#include <cuda_runtime.h>
#include <cuda.h>
#include <cstdint>
#include <cstddef>

#define IN_F   4096
#define OUT_F  11008
#define BATCH  32
#define N_TILE 32
#define K_TILE 64
#define STAGES 4
#define THREADS 128
#define NITER  (IN_F / K_TILE)      // 64

#define XROW    80                   // 64B data + 16B pad: bank-bijective LDS.32
#define XSTAGE  (64 * XROW)          // 5120 B per k-stage
#define WSTAGE  (N_TILE * K_TILE * 4)        // 8192 B (raw int32 words)
#define DSM_W   (STAGES * WSTAGE)            // 32768
#define DSM_X   (STAGES * XSTAGE)            // 20480
#define DSM_TOTAL (DSM_W + DSM_X)            // 53248
#define TX_BYTES (WSTAGE + XSTAGE)           // 13312 per stage

// g_xq tiled layout: [NITER][64 rows][XROW]; rows 0..31 = q1 plane, 32..63 = q2 plane
__device__ __align__(128) signed char g_xq[NITER * XSTAGE];

__global__ void quantize_x_kernel(const float* __restrict__ x) {
    int i = blockIdx.x * blockDim.x + threadIdx.x;      // i = b*4096 + k
    if (i >= BATCH * IN_F) return;
    int b = i >> 12, k = i & 4095;
    float v  = x[i];
    float q1 = rintf(v * 16.0f);
    q1 = fminf(fmaxf(q1, -127.0f), 127.0f);
    float r  = v - q1 * 0.0625f;
    float q2 = rintf(r * 4096.0f);
    q2 = fminf(fmaxf(q2, -127.0f), 127.0f);
    int tile = k >> 6, off = k & 63;
    signed char* base = g_xq + tile * XSTAGE + off;
    base[(size_t)b * XROW]        = (signed char)(int)q1;
    base[(size_t)(b + 32) * XROW] = (signed char)(int)q2;
}

__device__ __forceinline__ uint32_t smem_u32(const void* p) {
    return (uint32_t)__cvta_generic_to_shared(p);
}
__device__ __forceinline__ void mbar_init(uint32_t bar, uint32_t cnt) {
    asm volatile("mbarrier.init.shared.b64 [%0], %1;" :: "r"(bar), "r"(cnt) : "memory");
}
__device__ __forceinline__ void mbar_expect_tx(uint32_t bar, uint32_t bytes) {
    asm volatile("mbarrier.arrive.expect_tx.shared.b64 _, [%0], %1;"
                 :: "r"(bar), "r"(bytes) : "memory");
}
__device__ __forceinline__ void tma_load_2d(uint32_t sdst, const CUtensorMap* map,
                                            int cx, int cy, uint32_t bar) {
    asm volatile(
        "cp.async.bulk.tensor.2d.shared::cta.global.tile.mbarrier::complete_tx::bytes "
        "[%0], [%1, {%2, %3}], [%4];"
        :: "r"(sdst), "l"(map), "r"(cx), "r"(cy), "r"(bar) : "memory");
}
__device__ __forceinline__ void mbar_wait(uint32_t bar, uint32_t parity) {
    uint32_t done;
    asm volatile(
        "{\n\t.reg .pred p;\n\t"
        "mbarrier.try_wait.parity.acquire.cta.shared::cta.b64 p, [%1], %2;\n\t"
        "selp.b32 %0, 1, 0, p;\n\t}"
        : "=r"(done) : "r"(bar), "r"(parity) : "memory");
    if (!done) {
        asm volatile(
            "{\n\t.reg .pred P1;\n\t"
            "WAIT_LOOP_%=:\n\t"
            "mbarrier.try_wait.parity.acquire.cta.shared::cta.b64 P1, [%0], %1, 0x989680;\n\t"
            "@P1 bra.uni WAIT_DONE_%=;\n\t"
            "bra.uni WAIT_LOOP_%=;\n\t"
            "WAIT_DONE_%=:\n\t}"
            :: "r"(bar), "r"(parity) : "memory");
    }
}
__device__ __forceinline__ void mma_s8(int d[4], const int a[4], const int b[2]) {
    asm volatile(
        "mma.sync.aligned.m16n8k32.row.col.s32.s8.s8.s32 "
        "{%0,%1,%2,%3}, {%4,%5,%6,%7}, {%8,%9}, {%0,%1,%2,%3};"
        : "+r"(d[0]), "+r"(d[1]), "+r"(d[2]), "+r"(d[3])
        : "r"(a[0]), "r"(a[1]), "r"(a[2]), "r"(a[3]), "r"(b[0]), "r"(b[1]));
}

// W arrives as int32 words (low byte = int8 value). Both W and X stream via the
// TMA engine into a 4-deep ring (one mbarrier per stage, expect_tx covers both).
// Warps split 2x2 over (k-slice, n-half): halves X smem re-reads and per-warp
// issue; ks-partials are reduced through smem scratch at the end.
__global__ __launch_bounds__(THREADS, 3)
void qlinear_gemm_tma(const __grid_constant__ CUtensorMap tmap_w,
                      const __grid_constant__ CUtensorMap tmap_x,
                      const float* __restrict__ scale_p,
                      const float* __restrict__ bias,
                      float* __restrict__ out) {
    extern __shared__ __align__(128) char dsm[];
    char* wsm = dsm;            // [STAGES][32 rows][256B]
    char* xsm = dsm + DSM_W;    // [STAGES][64 rows][80B]
    __shared__ __align__(8) unsigned long long mbar_store[STAGES];

    const int tid  = threadIdx.x;
    const int n0   = blockIdx.x * N_TILE;
    const int lane = tid & 31;
    const int warp = tid >> 5;
    const int ksw  = warp & 1;       // k-slice: words [ksw*32, ksw*32+32) of the tile
    const int nh   = warp >> 1;      // n-half: cols [nh*16, nh*16+16)
    const int g    = lane >> 2;      // 0..7
    const int q    = lane & 3;       // 0..3
    const uint32_t mbar0 = smem_u32(mbar_store);

    if (tid == 0) {
        #pragma unroll
        for (int s = 0; s < STAGES; ++s) mbar_init(mbar0 + 8u * s, 1);
    }
    __syncthreads();

    // Prologue: fill STAGES-1 stages (W + X on one barrier each).
    if (tid == 0) {
        #pragma unroll
        for (int s = 0; s < STAGES - 1; ++s) {
            mbar_expect_tx(mbar0 + 8u * s, TX_BYTES);
            tma_load_2d(smem_u32(wsm) + s * WSTAGE, &tmap_w, s * K_TILE, n0, mbar0 + 8u * s);
            tma_load_2d(smem_u32(xsm) + s * XSTAGE, &tmap_x, 0, s * 64, mbar0 + 8u * s);
        }
    }

    int acc[4][2][4];   // [m_tile][n_frag][reg]; t 0..1 = q1 plane, 2..3 = q2 plane
    #pragma unroll
    for (int t = 0; t < 4; ++t)
        #pragma unroll
        for (int f = 0; f < 2; ++f)
            #pragma unroll
            for (int r = 0; r < 4; ++r) acc[t][f][r] = 0;

    const int kb = ksw * 32 + q * 4;

    for (int it = 0; it < NITER; ++it) {
        const int s = it & (STAGES - 1);
        mbar_wait(mbar0 + 8u * s, (it >> 2) & 1);
        __syncthreads();

        // Refill the stage consumed in the previous iteration.
        const int pf = it + STAGES - 1;
        if (tid == 0 && pf < NITER) {
            const int b = pf & (STAGES - 1);
            mbar_expect_tx(mbar0 + 8u * b, TX_BYTES);
            tma_load_2d(smem_u32(wsm) + b * WSTAGE, &tmap_w, pf * K_TILE, n0, mbar0 + 8u * b);
            tma_load_2d(smem_u32(xsm) + b * XSTAGE, &tmap_x, 0, pf * 64, mbar0 + 8u * b);
        }

        const char* wst = wsm + s * WSTAGE;
        const char* xst = xsm + s * XSTAGE;

        int a[4][4];
        #pragma unroll
        for (int t = 0; t < 4; ++t) {
            const char* xr = xst + (t * 16 + g) * XROW;
            a[t][0] = *(const int*)(xr + kb);
            a[t][1] = *(const int*)(xr + 8 * XROW + kb);
            a[t][2] = *(const int*)(xr + kb + 16);
            a[t][3] = *(const int*)(xr + 8 * XROW + kb + 16);
        }
        #pragma unroll
        for (int f = 0; f < 2; ++f) {
            const int nloc = nh * 16 + f * 8 + g;
            const char* wr = wst + nloc * 256 + ksw * 128 + q * 16;
            const int4 w0 = *(const int4*)wr;          // words kb..kb+3
            const int4 w1 = *(const int4*)(wr + 64);   // words kb+16..kb+19
            int b[2];
            b[0] = __byte_perm(__byte_perm(w0.x, w0.y, 0x0040),
                               __byte_perm(w0.z, w0.w, 0x0040), 0x5410);
            b[1] = __byte_perm(__byte_perm(w1.x, w1.y, 0x0040),
                               __byte_perm(w1.z, w1.w, 0x0040), 0x5410);
            #pragma unroll
            for (int t = 0; t < 4; ++t)
                mma_s8(acc[t][f], a[t], b);
        }
    }

    // Cross-warp ks reduction through smem scratch (reuses the W ring area).
    __syncthreads();
    int4* scratch = (int4*)(dsm + nh * 4096);
    if (ksw == 1) {
        #pragma unroll
        for (int t = 0; t < 4; ++t)
            #pragma unroll
            for (int f = 0; f < 2; ++f)
                scratch[(t * 2 + f) * 32 + lane] =
                    make_int4(acc[t][f][0], acc[t][f][1], acc[t][f][2], acc[t][f][3]);
    }
    __syncthreads();
    if (ksw == 0) {
        #pragma unroll
        for (int t = 0; t < 4; ++t)
            #pragma unroll
            for (int f = 0; f < 2; ++f) {
                const int4 p = scratch[(t * 2 + f) * 32 + lane];
                acc[t][f][0] += p.x; acc[t][f][1] += p.y;
                acc[t][f][2] += p.z; acc[t][f][3] += p.w;
            }

        // Epilogue: out = scale * (acc_hi/16 + acc_lo/4096) + bias
        const float sc = __ldg(scale_p);
        const float s1 = 0.0625f;
        const float s2 = 1.0f / 4096.0f;
        #pragma unroll
        for (int t = 0; t < 2; ++t)
            #pragma unroll
            for (int f = 0; f < 2; ++f) {
                const int n = n0 + nh * 16 + f * 8 + q * 2;
                const float2 bb = *(const float2*)&bias[n];
                const int r0 = t * 16 + g;
                const int r1 = r0 + 8;
                float v0 = fmaf(sc, fmaf(s1, (float)acc[t][f][0], s2 * (float)acc[t + 2][f][0]), bb.x);
                float v1 = fmaf(sc, fmaf(s1, (float)acc[t][f][1], s2 * (float)acc[t + 2][f][1]), bb.y);
                float v2 = fmaf(sc, fmaf(s1, (float)acc[t][f][2], s2 * (float)acc[t + 2][f][2]), bb.x);
                float v3 = fmaf(sc, fmaf(s1, (float)acc[t][f][3], s2 * (float)acc[t + 2][f][3]), bb.y);
                *(float2*)&out[(size_t)r0 * OUT_F + n] = make_float2(v0, v1);
                *(float2*)&out[(size_t)r1 * OUT_F + n] = make_float2(v2, v3);
            }
    }
}

typedef CUresult (*EncodeTiledFn)(
    CUtensorMap*, CUtensorMapDataType, cuuint32_t, void*,
    const cuuint64_t*, const cuuint64_t*, const cuuint32_t*, const cuuint32_t*,
    CUtensorMapInterleave, CUtensorMapSwizzle, CUtensorMapL2promotion,
    CUtensorMapFloatOOBfill);

extern "C" void kernel_launch(void* const* d_in, const int* in_sizes, int n_in,
                              void* d_out, int out_size) {
    // Bind inputs by element count (ordering-proof): all four counts are distinct.
    const float* x = nullptr; void* w = nullptr;
    const float* scale = nullptr; const float* bias = nullptr;
    for (int i = 0; i < n_in; ++i) {
        switch (in_sizes[i]) {
            case BATCH * IN_F:    x     = (const float*)d_in[i]; break;
            case OUT_F * IN_F:    w     = (void*)d_in[i];        break;
            case 1:               scale = (const float*)d_in[i]; break;
            case OUT_F:           bias  = (const float*)d_in[i]; break;
        }
    }
    float* out = (float*)d_out;

    static EncodeTiledFn encode_fn = nullptr;
    static bool attr_done = false;
    if (!encode_fn) {
        cudaDriverEntryPointQueryResult qr;
        void* fp = nullptr;
        cudaGetDriverEntryPoint("cuTensorMapEncodeTiled", &fp,
                                cudaEnableDefault, &qr);
        encode_fn = (EncodeTiledFn)fp;
    }
    if (!attr_done) {
        cudaFuncSetAttribute(qlinear_gemm_tma,
                             cudaFuncAttributeMaxDynamicSharedMemorySize, DSM_TOTAL);
        attr_done = true;
    }

    // W map: uint32 words, dims [IN_F, OUT_F], box [K_TILE, N_TILE].
    CUtensorMap tmap_w;
    {
        cuuint64_t dims[2]    = {IN_F, OUT_F};
        cuuint64_t strides[1] = {IN_F * sizeof(int)};
        cuuint32_t box[2]     = {K_TILE, N_TILE};
        cuuint32_t estr[2]    = {1, 1};
        encode_fn(&tmap_w, CU_TENSOR_MAP_DATA_TYPE_UINT32, 2, w,
                  dims, strides, box, estr,
                  CU_TENSOR_MAP_INTERLEAVE_NONE, CU_TENSOR_MAP_SWIZZLE_NONE,
                  CU_TENSOR_MAP_L2_PROMOTION_L2_128B, CU_TENSOR_MAP_FLOAT_OOB_FILL_NONE);
    }
    // X map over g_xq: uint32 words, dims [20 words/row, NITER*64 rows],
    // box [20, 64] = one padded 5120B stage; coord (0, tile*64).
    CUtensorMap tmap_x;
    {
        void* xq_dev = nullptr;
        cudaGetSymbolAddress(&xq_dev, g_xq);
        cuuint64_t dims[2]    = {XROW / 4, (cuuint64_t)NITER * 64};
        cuuint64_t strides[1] = {XROW};
        cuuint32_t box[2]     = {XROW / 4, 64};
        cuuint32_t estr[2]    = {1, 1};
        encode_fn(&tmap_x, CU_TENSOR_MAP_DATA_TYPE_UINT32, 2, xq_dev,
                  dims, strides, box, estr,
                  CU_TENSOR_MAP_INTERLEAVE_NONE, CU_TENSOR_MAP_SWIZZLE_NONE,
                  CU_TENSOR_MAP_L2_PROMOTION_L2_128B, CU_TENSOR_MAP_FLOAT_OOB_FILL_NONE);
    }

    quantize_x_kernel<<<(BATCH * IN_F + 255) / 256, 256>>>(x);
    qlinear_gemm_tma<<<OUT_F / N_TILE, THREADS, DSM_TOTAL>>>(tmap_w, tmap_x, scale, bias, out);
}

// round 11
// speedup vs baseline: 1.6825x; 1.0043x over previous
#include <cuda_runtime.h>
#include <cuda.h>
#include <cstdint>
#include <cstddef>

#define IN_F   4096
#define OUT_F  11008
#define BATCH  32
#define N_TILE 32
#define K_TILE 64
#define STAGES 4
#define THREADS 128
#define NITER  (IN_F / K_TILE)      // 64

// X fragment-packed layout: [tile][ksw][lane][t][16B], lane stride 80B
// (64B data + 16B pad -> bank-bijective LDS.128).
#define XSTAGE  5120                 // 2 ksw * 32 lanes * 80 B
#define WSTAGE  (N_TILE * K_TILE * 4)        // 8192 B (raw int32 words)
#define DSM_W   (STAGES * WSTAGE)            // 32768
#define DSM_X   (STAGES * XSTAGE)            // 20480
#define DSM_TOTAL (DSM_W + DSM_X)            // 53248
#define TX_BYTES (WSTAGE + XSTAGE)           // 13312 per stage

__device__ __align__(128) signed char g_xq[NITER * XSTAGE];

// Writes x in mma-fragment order so the GEMM loads each a-fragment with one
// LDS.128. Two-level residual: q1 = rint(16x), q2 = rint(4096*(x - q1/16)).
__global__ void quantize_x_kernel(const float* __restrict__ x) {
    int i = blockIdx.x * blockDim.x + threadIdx.x;      // i = b*4096 + k
    if (i >= BATCH * IN_F) return;
    int b = i >> 12, k = i & 4095;
    float v  = x[i];
    float q1 = rintf(v * 16.0f);
    q1 = fminf(fmaxf(q1, -127.0f), 127.0f);
    float r  = v - q1 * 0.0625f;
    float q2 = rintf(r * 4096.0f);
    q2 = fminf(fmaxf(q2, -127.0f), 127.0f);

    int tile = k >> 6, kl = k & 63;
    int ksw  = kl >> 5, rem = kl & 31;
    int o    = rem & 3;
    int q    = (rem >> 2) & 3;
    int hi16 = rem >> 4;                 // 0/1: k-offset +16 within slice
    int g    = b & 7;
    int rl   = (b >> 3) & 1;             // row +8
    int th   = b >> 4;                   // m-tile within plane (0/1)
    int j    = (rl + 2 * hi16) * 4 + o;  // byte index within 16B fragment
    int lane = g * 4 + q;

    signed char* base = g_xq + tile * XSTAGE + ksw * 2560 + lane * 80 + j;
    base[th * 16]       = (signed char)(int)q1;   // t = th   (q1 plane)
    base[(th + 2) * 16] = (signed char)(int)q2;   // t = th+2 (q2 plane)
}

__device__ __forceinline__ uint32_t smem_u32(const void* p) {
    return (uint32_t)__cvta_generic_to_shared(p);
}
__device__ __forceinline__ void mbar_init(uint32_t bar, uint32_t cnt) {
    asm volatile("mbarrier.init.shared.b64 [%0], %1;" :: "r"(bar), "r"(cnt) : "memory");
}
__device__ __forceinline__ void mbar_expect_tx(uint32_t bar, uint32_t bytes) {
    asm volatile("mbarrier.arrive.expect_tx.shared.b64 _, [%0], %1;"
                 :: "r"(bar), "r"(bytes) : "memory");
}
__device__ __forceinline__ void tma_load_2d(uint32_t sdst, const CUtensorMap* map,
                                            int cx, int cy, uint32_t bar) {
    asm volatile(
        "cp.async.bulk.tensor.2d.shared::cta.global.tile.mbarrier::complete_tx::bytes "
        "[%0], [%1, {%2, %3}], [%4];"
        :: "r"(sdst), "l"(map), "r"(cx), "r"(cy), "r"(bar) : "memory");
}
__device__ __forceinline__ void mbar_wait(uint32_t bar, uint32_t parity) {
    uint32_t done;
    asm volatile(
        "{\n\t.reg .pred p;\n\t"
        "mbarrier.try_wait.parity.acquire.cta.shared::cta.b64 p, [%1], %2;\n\t"
        "selp.b32 %0, 1, 0, p;\n\t}"
        : "=r"(done) : "r"(bar), "r"(parity) : "memory");
    if (!done) {
        asm volatile(
            "{\n\t.reg .pred P1;\n\t"
            "WAIT_LOOP_%=:\n\t"
            "mbarrier.try_wait.parity.acquire.cta.shared::cta.b64 P1, [%0], %1, 0x989680;\n\t"
            "@P1 bra.uni WAIT_DONE_%=;\n\t"
            "bra.uni WAIT_LOOP_%=;\n\t"
            "WAIT_DONE_%=:\n\t}"
            :: "r"(bar), "r"(parity) : "memory");
    }
}
__device__ __forceinline__ void mma_s8(int d[4], const int a[4], const int b[2]) {
    asm volatile(
        "mma.sync.aligned.m16n8k32.row.col.s32.s8.s8.s32 "
        "{%0,%1,%2,%3}, {%4,%5,%6,%7}, {%8,%9}, {%0,%1,%2,%3};"
        : "+r"(d[0]), "+r"(d[1]), "+r"(d[2]), "+r"(d[3])
        : "r"(a[0]), "r"(a[1]), "r"(a[2]), "r"(a[3]), "r"(b[0]), "r"(b[1]));
}

// W arrives as int32 words (low byte = int8 value). W and X stream via TMA into
// a 4-deep ring (one mbarrier per stage). Warps split 2x2 over (k-slice,
// n-half); a-fragments are single LDS.128 thanks to the packed X layout.
__global__ __launch_bounds__(THREADS, 4)
void qlinear_gemm_tma(const __grid_constant__ CUtensorMap tmap_w,
                      const __grid_constant__ CUtensorMap tmap_x,
                      const float* __restrict__ scale_p,
                      const float* __restrict__ bias,
                      float* __restrict__ out) {
    extern __shared__ __align__(128) char dsm[];
    char* wsm = dsm;            // [STAGES][32 rows][256B]
    char* xsm = dsm + DSM_W;    // [STAGES][2][32][80B]
    __shared__ __align__(8) unsigned long long mbar_store[STAGES];

    const int tid  = threadIdx.x;
    const int n0   = blockIdx.x * N_TILE;
    const int lane = tid & 31;
    const int warp = tid >> 5;
    const int ksw  = warp & 1;       // k-slice: words [ksw*32, ksw*32+32)
    const int nh   = warp >> 1;      // n-half: cols [nh*16, nh*16+16)
    const int g    = lane >> 2;      // 0..7
    const int q    = lane & 3;       // 0..3
    const uint32_t mbar0 = smem_u32(mbar_store);

    if (tid == 0) {
        #pragma unroll
        for (int s = 0; s < STAGES; ++s) mbar_init(mbar0 + 8u * s, 1);
    }
    __syncthreads();

    if (tid == 0) {
        #pragma unroll
        for (int s = 0; s < STAGES - 1; ++s) {
            mbar_expect_tx(mbar0 + 8u * s, TX_BYTES);
            tma_load_2d(smem_u32(wsm) + s * WSTAGE, &tmap_w, s * K_TILE, n0, mbar0 + 8u * s);
            tma_load_2d(smem_u32(xsm) + s * XSTAGE, &tmap_x, 0, s * 64, mbar0 + 8u * s);
        }
    }

    int acc[4][2][4];   // [m_tile][n_frag][reg]; t 0..1 = q1 plane, 2..3 = q2 plane
    #pragma unroll
    for (int t = 0; t < 4; ++t)
        #pragma unroll
        for (int f = 0; f < 2; ++f)
            #pragma unroll
            for (int r = 0; r < 4; ++r) acc[t][f][r] = 0;

    const int xoff = ksw * 2560 + lane * 80;

    for (int it = 0; it < NITER; ++it) {
        const int s = it & (STAGES - 1);
        mbar_wait(mbar0 + 8u * s, (it >> 2) & 1);
        __syncthreads();

        const int pf = it + STAGES - 1;
        if (tid == 0 && pf < NITER) {
            const int b = pf & (STAGES - 1);
            mbar_expect_tx(mbar0 + 8u * b, TX_BYTES);
            tma_load_2d(smem_u32(wsm) + b * WSTAGE, &tmap_w, pf * K_TILE, n0, mbar0 + 8u * b);
            tma_load_2d(smem_u32(xsm) + b * XSTAGE, &tmap_x, 0, pf * 64, mbar0 + 8u * b);
        }

        const char* wst = wsm + s * WSTAGE;
        const char* xfr = xsm + s * XSTAGE + xoff;

        int a[4][4];
        #pragma unroll
        for (int t = 0; t < 4; ++t)
            *(int4*)a[t] = *(const int4*)(xfr + t * 16);

        #pragma unroll
        for (int f = 0; f < 2; ++f) {
            const int nloc = nh * 16 + f * 8 + g;
            const char* wr = wst + nloc * 256 + ksw * 128 + q * 16;
            const int4 w0 = *(const int4*)wr;          // words kb..kb+3
            const int4 w1 = *(const int4*)(wr + 64);   // words kb+16..kb+19
            int b[2];
            b[0] = __byte_perm(__byte_perm(w0.x, w0.y, 0x0040),
                               __byte_perm(w0.z, w0.w, 0x0040), 0x5410);
            b[1] = __byte_perm(__byte_perm(w1.x, w1.y, 0x0040),
                               __byte_perm(w1.z, w1.w, 0x0040), 0x5410);
            #pragma unroll
            for (int t = 0; t < 4; ++t)
                mma_s8(acc[t][f], a[t], b);
        }
    }

    // Cross-warp ks reduction through smem scratch (reuses the W ring area).
    __syncthreads();
    int4* scratch = (int4*)(dsm + nh * 4096);
    if (ksw == 1) {
        #pragma unroll
        for (int t = 0; t < 4; ++t)
            #pragma unroll
            for (int f = 0; f < 2; ++f)
                scratch[(t * 2 + f) * 32 + lane] =
                    make_int4(acc[t][f][0], acc[t][f][1], acc[t][f][2], acc[t][f][3]);
    }
    __syncthreads();
    if (ksw == 0) {
        #pragma unroll
        for (int t = 0; t < 4; ++t)
            #pragma unroll
            for (int f = 0; f < 2; ++f) {
                const int4 p = scratch[(t * 2 + f) * 32 + lane];
                acc[t][f][0] += p.x; acc[t][f][1] += p.y;
                acc[t][f][2] += p.z; acc[t][f][3] += p.w;
            }

        // Epilogue: out = scale * (acc_hi/16 + acc_lo/4096) + bias
        const float sc = __ldg(scale_p);
        const float s1 = 0.0625f;
        const float s2 = 1.0f / 4096.0f;
        #pragma unroll
        for (int t = 0; t < 2; ++t)
            #pragma unroll
            for (int f = 0; f < 2; ++f) {
                const int n = n0 + nh * 16 + f * 8 + q * 2;
                const float2 bb = *(const float2*)&bias[n];
                const int r0 = t * 16 + g;
                const int r1 = r0 + 8;
                float v0 = fmaf(sc, fmaf(s1, (float)acc[t][f][0], s2 * (float)acc[t + 2][f][0]), bb.x);
                float v1 = fmaf(sc, fmaf(s1, (float)acc[t][f][1], s2 * (float)acc[t + 2][f][1]), bb.y);
                float v2 = fmaf(sc, fmaf(s1, (float)acc[t][f][2], s2 * (float)acc[t + 2][f][2]), bb.x);
                float v3 = fmaf(sc, fmaf(s1, (float)acc[t][f][3], s2 * (float)acc[t + 2][f][3]), bb.y);
                *(float2*)&out[(size_t)r0 * OUT_F + n] = make_float2(v0, v1);
                *(float2*)&out[(size_t)r1 * OUT_F + n] = make_float2(v2, v3);
            }
    }
}

typedef CUresult (*EncodeTiledFn)(
    CUtensorMap*, CUtensorMapDataType, cuuint32_t, void*,
    const cuuint64_t*, const cuuint64_t*, const cuuint32_t*, const cuuint32_t*,
    CUtensorMapInterleave, CUtensorMapSwizzle, CUtensorMapL2promotion,
    CUtensorMapFloatOOBfill);

extern "C" void kernel_launch(void* const* d_in, const int* in_sizes, int n_in,
                              void* d_out, int out_size) {
    // Bind inputs by element count (ordering-proof): all four counts are distinct.
    const float* x = nullptr; void* w = nullptr;
    const float* scale = nullptr; const float* bias = nullptr;
    for (int i = 0; i < n_in; ++i) {
        switch (in_sizes[i]) {
            case BATCH * IN_F:    x     = (const float*)d_in[i]; break;
            case OUT_F * IN_F:    w     = (void*)d_in[i];        break;
            case 1:               scale = (const float*)d_in[i]; break;
            case OUT_F:           bias  = (const float*)d_in[i]; break;
        }
    }
    float* out = (float*)d_out;

    static EncodeTiledFn encode_fn = nullptr;
    static bool attr_done = false;
    if (!encode_fn) {
        cudaDriverEntryPointQueryResult qr;
        void* fp = nullptr;
        cudaGetDriverEntryPoint("cuTensorMapEncodeTiled", &fp,
                                cudaEnableDefault, &qr);
        encode_fn = (EncodeTiledFn)fp;
    }
    if (!attr_done) {
        cudaFuncSetAttribute(qlinear_gemm_tma,
                             cudaFuncAttributeMaxDynamicSharedMemorySize, DSM_TOTAL);
        attr_done = true;
    }

    // W map: uint32 words, dims [IN_F, OUT_F], box [K_TILE, N_TILE].
    CUtensorMap tmap_w;
    {
        cuuint64_t dims[2]    = {IN_F, OUT_F};
        cuuint64_t strides[1] = {IN_F * sizeof(int)};
        cuuint32_t box[2]     = {K_TILE, N_TILE};
        cuuint32_t estr[2]    = {1, 1};
        encode_fn(&tmap_w, CU_TENSOR_MAP_DATA_TYPE_UINT32, 2, w,
                  dims, strides, box, estr,
                  CU_TENSOR_MAP_INTERLEAVE_NONE, CU_TENSOR_MAP_SWIZZLE_NONE,
                  CU_TENSOR_MAP_L2_PROMOTION_L2_128B, CU_TENSOR_MAP_FLOAT_OOB_FILL_NONE);
    }
    // X map over g_xq: rows of 80B (20 words), 64 rows per tile; box = one stage.
    CUtensorMap tmap_x;
    {
        void* xq_dev = nullptr;
        cudaGetSymbolAddress(&xq_dev, g_xq);
        cuuint64_t dims[2]    = {20, (cuuint64_t)NITER * 64};
        cuuint64_t strides[1] = {80};
        cuuint32_t box[2]     = {20, 64};
        cuuint32_t estr[2]    = {1, 1};
        encode_fn(&tmap_x, CU_TENSOR_MAP_DATA_TYPE_UINT32, 2, xq_dev,
                  dims, strides, box, estr,
                  CU_TENSOR_MAP_INTERLEAVE_NONE, CU_TENSOR_MAP_SWIZZLE_NONE,
                  CU_TENSOR_MAP_L2_PROMOTION_L2_128B, CU_TENSOR_MAP_FLOAT_OOB_FILL_NONE);
    }

    quantize_x_kernel<<<(BATCH * IN_F + 255) / 256, 256>>>(x);
    qlinear_gemm_tma<<<OUT_F / N_TILE, THREADS, DSM_TOTAL>>>(tmap_w, tmap_x, scale, bias, out);
}